// round 2
// baseline (speedup 1.0000x reference)
#include <cuda_runtime.h>
#include <cuda_bf16.h>
#include <cstdint>
#include <cstdio>

// ---------------------------------------------------------------------------
// FastAttention (Performer / FAVOR+) — fp32 SIMT tiled implementation
//   b=4, h=8 (BH=32), n=4096, d=64, m=266, e=64
// Pipeline:
//   k1: k_dash = dn * k @ P^T           (store 139MB scratch, global max, diag_k)
//   k2: kp = ratio*(exp(k_dash-diag-stab)+EPS);  context += kp^T @ v / L; kmean
//   k3: q_dash = dn * q @ P^T (smem);  per-row max/exp -> qp;  D_inv = 1/(qp.kmean)
//       out = D_inv * (qp @ context)
// ---------------------------------------------------------------------------

#define BH    32
#define NSEQ  4096
#define DDIM  64
#define MDIM  266
#define EDIM  64

constexpr float DN_F    = 0.35355339059327373f;  // 64^-0.25
constexpr float DIAG_C  = 0.0625f;               // 0.5 * DN^2
constexpr float RATIO_F = 0.06131393316f;        // 266^-0.5
constexpr float EPS_F   = 1e-4f;
constexpr float INV_L   = 1.0f / 4096.0f;

// ------------------------------ scratch ------------------------------------
__device__ __align__(16) float    g_kdash[(size_t)BH * NSEQ * MDIM]; // 139.5 MB
__device__ __align__(16) float    g_diag_k[BH * NSEQ];
__device__ unsigned               g_kmax_u;                          // flip-encoded max
__device__ __align__(16) float    g_context[BH * MDIM * EDIM];       // 2.18 MB
__device__ __align__(16) float    g_kmean[BH * MDIM];

// monotonic float<->uint encoding for atomicMax
__device__ __forceinline__ unsigned fenc(float f) {
    unsigned u = __float_as_uint(f);
    return (u & 0x80000000u) ? ~u : (u | 0x80000000u);
}
__device__ __forceinline__ float fdec(unsigned k) {
    return (k & 0x80000000u) ? __uint_as_float(k ^ 0x80000000u)
                             : __uint_as_float(~k);
}

// load a [rows<=64][64] row-major global tile TRANSPOSED into dst[c][r]
__device__ __forceinline__ void load_tile_T(float dst[64][72],
                                            const float* __restrict__ src,
                                            int row_valid, int tid) {
#pragma unroll
    for (int t = 0; t < 4; t++) {
        int idx = tid + t * 256;
        int r = idx >> 4, c4 = (idx & 15) << 2;
        float4 v;
        if (r < row_valid) v = *(const float4*)(src + (size_t)r * 64 + c4);
        else               v = make_float4(0.f, 0.f, 0.f, 0.f);
        dst[c4 + 0][r] = v.x; dst[c4 + 1][r] = v.y;
        dst[c4 + 2][r] = v.z; dst[c4 + 3][r] = v.w;
    }
}

__device__ __forceinline__ void fma16(float acc[4][4], float4 a, float4 b) {
    float av[4] = {a.x, a.y, a.z, a.w};
    float bv[4] = {b.x, b.y, b.z, b.w};
#pragma unroll
    for (int i = 0; i < 4; i++)
#pragma unroll
        for (int j = 0; j < 4; j++)
            acc[i][j] = fmaf(av[i], bv[j], acc[i][j]);
}

// ------------------------------ k0: init -----------------------------------
__global__ void k0_init() {
    int i = blockIdx.x * blockDim.x + threadIdx.x;
    int stride = gridDim.x * blockDim.x;
    if (i == 0) g_kmax_u = 0u;   // smaller than any encoded float
    for (int t = i; t < BH * MDIM * EDIM; t += stride) g_context[t] = 0.f;
    for (int t = i; t < BH * MDIM; t += stride)        g_kmean[t] = 0.f;
}

// ------------------------------ k1: k_dash ---------------------------------
__global__ __launch_bounds__(256) void k1_kdash(const float* __restrict__ K,
                                                const float* __restrict__ Pm) {
    __shared__ __align__(16) float Ks[64][72];   // [d][n-local]  (A transposed)
    __shared__ __align__(16) float Ps[64][72];   // [d][m-local]  (B transposed)
    __shared__ float red[8];

    int tid = threadIdx.x;
    int bh = blockIdx.y;
    int n0 = blockIdx.x << 6;

    load_tile_T(Ks, K + ((size_t)bh * NSEQ + n0) * DDIM, 64, tid);
    __syncthreads();

    if (tid < 64) {
        float s = 0.f;
#pragma unroll
        for (int c = 0; c < 64; c++) { float x = Ks[c][tid]; s += x * x; }
        g_diag_k[bh * NSEQ + n0 + tid] = DIAG_C * s;
    }

    int ty = tid >> 4, tx = tid & 15;
    float lmax = -3.0e38f;

    for (int mc = 0; mc < 5; ++mc) {
        int m0 = mc << 6;
        __syncthreads();
        load_tile_T(Ps, Pm + (size_t)m0 * DDIM, MDIM - m0, tid);
        __syncthreads();

        float acc[4][4];
#pragma unroll
        for (int i = 0; i < 4; i++)
#pragma unroll
            for (int j = 0; j < 4; j++) acc[i][j] = 0.f;

#pragma unroll 8
        for (int kk = 0; kk < 64; ++kk) {
            float4 a = *(const float4*)&Ks[kk][ty << 2];
            float4 b = *(const float4*)&Ps[kk][tx << 2];
            fma16(acc, a, b);
        }

        int mbase = m0 + (tx << 2);
#pragma unroll
        for (int i = 0; i < 4; i++) {
            float* orow = g_kdash +
                ((size_t)bh * NSEQ + n0 + (ty << 2) + i) * MDIM + mbase;
#pragma unroll
            for (int j = 0; j < 4; j++) {
                if (mbase + j < MDIM) {
                    float v = acc[i][j] * DN_F;
                    orow[j] = v;
                    lmax = fmaxf(lmax, v);
                }
            }
        }
    }

    // block max reduce -> global atomic
#pragma unroll
    for (int o = 16; o > 0; o >>= 1)
        lmax = fmaxf(lmax, __shfl_xor_sync(0xffffffffu, lmax, o));
    if ((tid & 31) == 0) red[tid >> 5] = lmax;
    __syncthreads();
    if (tid < 8) {
        lmax = red[tid];
        lmax = fmaxf(lmax, __shfl_xor_sync(0xffu, lmax, 1));
        lmax = fmaxf(lmax, __shfl_xor_sync(0xffu, lmax, 2));
        lmax = fmaxf(lmax, __shfl_xor_sync(0xffu, lmax, 4));
        if (tid == 0) atomicMax(&g_kmax_u, fenc(lmax));
    }
}

// ------------------------------ k2: context + kmean ------------------------
__global__ __launch_bounds__(256) void k2_context(const float* __restrict__ V) {
    __shared__ __align__(16) float kp_s[64][72]; // [n-local][m-local] (A^T for GEMM)
    __shared__ __align__(16) float v_s[64][72];  // [n-local][e]
    __shared__ float d_s[64];
    __shared__ float msum_s[64];

    int tid = threadIdx.x;
    int m0 = blockIdx.x << 6;
    int bh = blockIdx.y;
    int cbase = blockIdx.z << 4;     // 16 n-chunks per split

    float stab = fdec(g_kmax_u);
    if (tid < 64) msum_s[tid] = 0.f;

    int ty = tid >> 4, tx = tid & 15;
    int c = tid & 63, rr = tid >> 6;
    bool cvalid = (m0 + c) < MDIM;

    float acc[4][4];
#pragma unroll
    for (int i = 0; i < 4; i++)
#pragma unroll
        for (int j = 0; j < 4; j++) acc[i][j] = 0.f;

    for (int nc = 0; nc < 16; ++nc) {
        int n0 = (cbase + nc) << 6;
        __syncthreads();   // previous GEMM done with kp_s/v_s

        const float* vb = V + ((size_t)bh * NSEQ + n0) * EDIM;
#pragma unroll
        for (int t = 0; t < 4; t++) {
            int idx = tid + t * 256;
            int r = idx >> 4, c4 = (idx & 15) << 2;
            *(float4*)&v_s[r][c4] = *(const float4*)(vb + r * EDIM + c4);
        }
        if (tid < 64) d_s[tid] = g_diag_k[bh * NSEQ + n0 + tid];

        float raw[16];
        const float* kdb = g_kdash + ((size_t)bh * NSEQ + n0) * MDIM + m0 + c;
#pragma unroll
        for (int t = 0; t < 16; t++) {
            int r = rr + (t << 2);
            raw[t] = cvalid ? kdb[(size_t)r * MDIM] : 0.f;
        }
        __syncthreads();   // d_s, v_s ready

        float local = 0.f;
#pragma unroll
        for (int t = 0; t < 16; t++) {
            int r = rr + (t << 2);
            float val = RATIO_F * (__expf(raw[t] - d_s[r] - stab) + EPS_F);
            kp_s[r][c] = val;
            local += val;
        }
        atomicAdd(&msum_s[c], local);
        __syncthreads();   // kp_s ready

#pragma unroll 8
        for (int kk = 0; kk < 64; ++kk) {
            float4 a = *(const float4*)&kp_s[kk][ty << 2];
            float4 b = *(const float4*)&v_s[kk][tx << 2];
            fma16(acc, a, b);
        }
    }
    __syncthreads();

#pragma unroll
    for (int i = 0; i < 4; i++) {
        int m = m0 + (ty << 2) + i;
        if (m < MDIM) {
            float* crow = g_context + ((size_t)bh * MDIM + m) * EDIM + (tx << 2);
#pragma unroll
            for (int j = 0; j < 4; j++)
                atomicAdd(&crow[j], acc[i][j] * INV_L);
        }
    }
    if (tid < 64 && cvalid)
        atomicAdd(&g_kmean[bh * MDIM + m0 + tid], msum_s[tid] * INV_L);
}

// ------------------------------ k3: output ---------------------------------
constexpr int QP_STRIDE = 65;
// pad QP region to a multiple of 4 floats so Qs/Bs stay 16-byte aligned
constexpr int SM3_QP = ((MDIM * QP_STRIDE + 3) / 4) * 4;   // 17292 floats
constexpr int SM3_Q  = 64 * 72;                            // 4608 (mult of 4)
constexpr int SM3_B  = 64 * 72;
constexpr int SM3_KM = 272;
constexpr int SM3_FLOATS = SM3_QP + SM3_Q + SM3_B + SM3_KM + 64 + 64;
constexpr int SM3_BYTES  = SM3_FLOATS * 4;                 // 107,632 B

__global__ __launch_bounds__(256) void k3_out(const float* __restrict__ Q,
                                              const float* __restrict__ Pm,
                                              float* __restrict__ Out) {
    extern __shared__ __align__(16) float sm[];
    float* qp = sm;                                        // [266][65]
    float (*Qs)[72] = (float(*)[72])(sm + SM3_QP);
    float (*Bs)[72] = (float(*)[72])(sm + SM3_QP + SM3_Q);
    float* km_s = sm + SM3_QP + SM3_Q + SM3_B;
    float* dq   = km_s + SM3_KM;
    float* dinv = dq + 64;

    int tid = threadIdx.x;
    int bh = blockIdx.y;
    int n0 = blockIdx.x << 6;

    load_tile_T(Qs, Q + ((size_t)bh * NSEQ + n0) * DDIM, 64, tid);
    for (int i = tid; i < MDIM; i += 256) km_s[i] = g_kmean[bh * MDIM + i];
    __syncthreads();

    if (tid < 64) {
        float s = 0.f;
#pragma unroll
        for (int cc = 0; cc < 64; cc++) { float x = Qs[cc][tid]; s += x * x; }
        dq[tid] = DIAG_C * s;
    }

    int ty = tid >> 4, tx = tid & 15;

    // ---- phase 1: q_dash into qp (stored [m][r] for phase-3 GEMM) ----
    for (int mc = 0; mc < 5; ++mc) {
        int m0 = mc << 6;
        __syncthreads();
        load_tile_T(Bs, Pm + (size_t)m0 * DDIM, MDIM - m0, tid);
        __syncthreads();

        float acc[4][4];
#pragma unroll
        for (int i = 0; i < 4; i++)
#pragma unroll
            for (int j = 0; j < 4; j++) acc[i][j] = 0.f;

#pragma unroll 8
        for (int kk = 0; kk < 64; ++kk) {
            float4 a = *(const float4*)&Qs[kk][ty << 2];
            float4 b = *(const float4*)&Bs[kk][tx << 2];
            fma16(acc, a, b);
        }
#pragma unroll
        for (int j = 0; j < 4; j++) {
            int m = m0 + (tx << 2) + j;
            if (m < MDIM) {
#pragma unroll
                for (int i = 0; i < 4; i++)
                    qp[m * QP_STRIDE + (ty << 2) + i] = acc[i][j] * DN_F;
            }
        }
    }
    __syncthreads();

    // ---- phase 2: per-row max, exp transform, D_inv ----
    {
        int r = tid >> 2, g = tid & 3;     // 4 threads per row
        float mx = -3.0e38f;
        for (int cc = g; cc < MDIM; cc += 4)
            mx = fmaxf(mx, qp[cc * QP_STRIDE + r]);
        mx = fmaxf(mx, __shfl_xor_sync(0xffffffffu, mx, 1));
        mx = fmaxf(mx, __shfl_xor_sync(0xffffffffu, mx, 2));

        float dqr = dq[r];
        float dsum = 0.f;
        for (int cc = g; cc < MDIM; cc += 4) {
            float val = RATIO_F * (__expf(qp[cc * QP_STRIDE + r] - dqr - mx) + EPS_F);
            qp[cc * QP_STRIDE + r] = val;
            dsum += val * km_s[cc];
        }
        dsum += __shfl_xor_sync(0xffffffffu, dsum, 1);
        dsum += __shfl_xor_sync(0xffffffffu, dsum, 2);
        if (g == 0) dinv[r] = 1.0f / dsum;
    }
    __syncthreads();

    // ---- phase 3: out = (qp @ context) * dinv ----
    float acc[4][4];
#pragma unroll
    for (int i = 0; i < 4; i++)
#pragma unroll
        for (int j = 0; j < 4; j++) acc[i][j] = 0.f;

    for (int kc = 0; kc < 5; ++kc) {
        int k0 = kc << 6;
        int kend = min(64, MDIM - k0);
        __syncthreads();
#pragma unroll
        for (int t = 0; t < 4; t++) {
            int idx = tid + t * 256;
            int r = idx >> 4, c4 = (idx & 15) << 2;
            if (r < kend)
                *(float4*)&Bs[r][c4] = *(const float4*)(
                    g_context + ((size_t)bh * MDIM + k0 + r) * EDIM + c4);
        }
        __syncthreads();

#pragma unroll 4
        for (int kk = 0; kk < kend; ++kk) {
            const float* qrow = &qp[(k0 + kk) * QP_STRIDE + (ty << 2)];
            float4 a = make_float4(qrow[0], qrow[1], qrow[2], qrow[3]);
            float4 b = *(const float4*)&Bs[kk][tx << 2];
            fma16(acc, a, b);
        }
    }

#pragma unroll
    for (int i = 0; i < 4; i++) {
        float di = dinv[(ty << 2) + i];
        float4 o;
        o.x = acc[i][0] * di; o.y = acc[i][1] * di;
        o.z = acc[i][2] * di; o.w = acc[i][3] * di;
        *(float4*)(Out + ((size_t)bh * NSEQ + n0 + (ty << 2) + i) * EDIM +
                   (tx << 2)) = o;
    }
}

// ------------------------------ launch -------------------------------------
extern "C" void kernel_launch(void* const* d_in, const int* in_sizes, int n_in,
                              void* d_out, int out_size) {
    const float* q = (const float*)d_in[0];
    const float* k = (const float*)d_in[1];
    const float* v = (const float*)d_in[2];
    const float* P = (const float*)d_in[3];
    float* out = (float*)d_out;

    cudaFuncSetAttribute(k3_out, cudaFuncAttributeMaxDynamicSharedMemorySize,
                         SM3_BYTES);

    k0_init<<<256, 256>>>();
    k1_kdash<<<dim3(NSEQ / 64, BH), 256>>>(k, P);
    k2_context<<<dim3(5, BH, 4), 256>>>(v);
    k3_out<<<dim3(NSEQ / 64, BH), 256, SM3_BYTES>>>(q, P, out);
}

// round 5
// speedup vs baseline: 3.7907x; 3.7907x over previous
#include <cuda_runtime.h>
#include <cuda_bf16.h>
#include <cstdint>

// ---------------------------------------------------------------------------
// FastAttention (Performer / FAVOR+) — TF32 warp-MMA implementation
//   b=4, h=8 (BH=32), n=4096, d=64, m=266, e=64
//   All 4 GEMMs on mma.sync.m16n8k8.tf32 (HMMA). fp32 accum, fp32 diag/exp.
// ---------------------------------------------------------------------------

#define BH    32
#define NSEQ  4096
#define DDIM  64
#define MDIM  266
#define EDIM  64
#define MPAD  272      // 17 * 16 — padded m for k3 qp buffer

constexpr float DN_F    = 0.35355339059327373f;  // 64^-0.25
constexpr float DIAG_C  = 0.0625f;               // 0.5 * DN^2
constexpr float RATIO_F = 0.06131393316f;        // 266^-0.5
constexpr float EPS_F   = 1e-4f;
constexpr float INV_L   = 1.0f / 4096.0f;

// ------------------------------ scratch ------------------------------------
__device__ __align__(16) float    g_kdash[(size_t)BH * NSEQ * MDIM]; // 139.5 MB
__device__ __align__(16) float    g_diag_k[BH * NSEQ];
__device__ unsigned               g_kmax_u;
__device__ __align__(16) float    g_context[BH * MDIM * EDIM];
__device__ __align__(16) float    g_kmean[BH * MDIM];

__device__ __forceinline__ unsigned fenc(float f) {
    unsigned u = __float_as_uint(f);
    return (u & 0x80000000u) ? ~u : (u | 0x80000000u);
}
__device__ __forceinline__ float fdec(unsigned k) {
    return (k & 0x80000000u) ? __uint_as_float(k ^ 0x80000000u)
                             : __uint_as_float(~k);
}
__device__ __forceinline__ unsigned f2tf(float x) {
    unsigned r;
    asm("cvt.rna.tf32.f32 %0, %1;" : "=r"(r) : "f"(x));
    return r;
}
// D += A(16x8,row) * B(8x8,col)  — tf32
__device__ __forceinline__ void mma8(float* c, unsigned a0, unsigned a1,
                                     unsigned a2, unsigned a3,
                                     unsigned b0, unsigned b1) {
    asm volatile(
        "mma.sync.aligned.m16n8k8.row.col.f32.tf32.tf32.f32 "
        "{%0,%1,%2,%3}, {%4,%5,%6,%7}, {%8,%9}, {%0,%1,%2,%3};"
        : "+f"(c[0]), "+f"(c[1]), "+f"(c[2]), "+f"(c[3])
        : "r"(a0), "r"(a1), "r"(a2), "r"(a3), "r"(b0), "r"(b1));
}

// 64x64 fp32 tile, row-major -> tf32 bits in dst[64][72]; zero-pad rows>=valid
__device__ __forceinline__ void load_tile(unsigned (*dst)[72],
                                          const float* __restrict__ src,
                                          int valid, int tid) {
#pragma unroll
    for (int t = 0; t < 4; t++) {
        int idx = tid + (t << 8);
        int r = idx >> 4, c4 = (idx & 15) << 2;
        float4 v = (r < valid) ? *(const float4*)(src + (size_t)r * 64 + c4)
                               : make_float4(0.f, 0.f, 0.f, 0.f);
        uint4 u;
        u.x = f2tf(v.x); u.y = f2tf(v.y); u.z = f2tf(v.z); u.w = f2tf(v.w);
        *(uint4*)&dst[r][c4] = u;
    }
}
// same (64 valid rows) + DIAG_C * sum(row^2) of ORIGINAL fp32 -> diag_out[r]
__device__ __forceinline__ void load_tile_diag(unsigned (*dst)[72],
                                               const float* __restrict__ src,
                                               int tid, float* diag_out) {
#pragma unroll
    for (int t = 0; t < 4; t++) {
        int idx = tid + (t << 8);
        int r = idx >> 4, c4 = (idx & 15) << 2;
        float4 v = *(const float4*)(src + (size_t)r * 64 + c4);
        float s = v.x * v.x + v.y * v.y + v.z * v.z + v.w * v.w;
        s += __shfl_xor_sync(0xffffffffu, s, 1);
        s += __shfl_xor_sync(0xffffffffu, s, 2);
        s += __shfl_xor_sync(0xffffffffu, s, 4);
        s += __shfl_xor_sync(0xffffffffu, s, 8);
        uint4 u;
        u.x = f2tf(v.x); u.y = f2tf(v.y); u.z = f2tf(v.z); u.w = f2tf(v.w);
        *(uint4*)&dst[r][c4] = u;
        if ((tid & 15) == 0) diag_out[r] = DIAG_C * s;
    }
}

// ------------------------------ k0: init -----------------------------------
__global__ void k0_init() {
    int i = blockIdx.x * blockDim.x + threadIdx.x;
    int stride = gridDim.x * blockDim.x;
    if (i == 0) g_kmax_u = 0u;
    for (int t = i; t < BH * MDIM * EDIM; t += stride) g_context[t] = 0.f;
    for (int t = i; t < BH * MDIM; t += stride)        g_kmean[t] = 0.f;
}

// ------------------------------ k1: k_dash ---------------------------------
__global__ __launch_bounds__(256) void k1_kdash(const float* __restrict__ K,
                                                const float* __restrict__ Pm) {
    __shared__ __align__(16) unsigned Ks[64][72];   // [n-local][d] tf32
    __shared__ __align__(16) unsigned Ps[64][72];   // [m-local][d] tf32
    __shared__ float red[8];

    int tid = threadIdx.x, lane = tid & 31, warp = tid >> 5;
    int g = lane >> 2, tg = lane & 3;
    int bh = blockIdx.y, n0 = blockIdx.x << 6;
    int rb = (warp & 1) << 5;        // n rows 32*wn
    int cb = (warp >> 1) << 4;       // m cols 16*wm

    load_tile_diag(Ks, K + ((size_t)bh * NSEQ + n0) * DDIM, tid,
                   g_diag_k + bh * NSEQ + n0);

    float lmax = -3.0e38f;
    for (int mc = 0; mc < 5; mc++) {
        int m0 = mc << 6;
        __syncthreads();
        load_tile(Ps, Pm + (size_t)m0 * DDIM, MDIM - m0, tid);
        __syncthreads();

        float c[2][2][4];
#pragma unroll
        for (int i = 0; i < 2; i++)
#pragma unroll
            for (int j = 0; j < 2; j++)
#pragma unroll
                for (int q = 0; q < 4; q++) c[i][j][q] = 0.f;

#pragma unroll
        for (int ks = 0; ks < 8; ks++) {
            int k0 = ks << 3;
            unsigned a[2][4], b[2][2];
#pragma unroll
            for (int i = 0; i < 2; i++) {
                int r0 = rb + (i << 4);
                a[i][0] = Ks[r0 + g][k0 + tg];
                a[i][1] = Ks[r0 + g + 8][k0 + tg];
                a[i][2] = Ks[r0 + g][k0 + tg + 4];
                a[i][3] = Ks[r0 + g + 8][k0 + tg + 4];
            }
#pragma unroll
            for (int j = 0; j < 2; j++) {
                int mcol = cb + (j << 3) + g;
                b[j][0] = Ps[mcol][k0 + tg];
                b[j][1] = Ps[mcol][k0 + tg + 4];
            }
#pragma unroll
            for (int i = 0; i < 2; i++)
#pragma unroll
                for (int j = 0; j < 2; j++)
                    mma8(c[i][j], a[i][0], a[i][1], a[i][2], a[i][3],
                         b[j][0], b[j][1]);
        }

#pragma unroll
        for (int i = 0; i < 2; i++) {
            int row = n0 + rb + (i << 4) + g;
#pragma unroll
            for (int j = 0; j < 2; j++) {
                int m = m0 + cb + (j << 3) + (tg << 1);
                if (m < MDIM) {   // m even; pair (m,m+1) fully valid (MDIM even)
                    float2 v0 = make_float2(c[i][j][0] * DN_F, c[i][j][1] * DN_F);
                    float2 v1 = make_float2(c[i][j][2] * DN_F, c[i][j][3] * DN_F);
                    lmax = fmaxf(lmax, fmaxf(fmaxf(v0.x, v0.y), fmaxf(v1.x, v1.y)));
                    *(float2*)(g_kdash + ((size_t)bh * NSEQ + row) * MDIM + m)     = v0;
                    *(float2*)(g_kdash + ((size_t)bh * NSEQ + row + 8) * MDIM + m) = v1;
                }
            }
        }
    }

#pragma unroll
    for (int o = 16; o > 0; o >>= 1)
        lmax = fmaxf(lmax, __shfl_xor_sync(0xffffffffu, lmax, o));
    if (lane == 0) red[warp] = lmax;
    __syncthreads();
    if (tid < 8) {
        lmax = red[tid];
        lmax = fmaxf(lmax, __shfl_xor_sync(0xffu, lmax, 1));
        lmax = fmaxf(lmax, __shfl_xor_sync(0xffu, lmax, 2));
        lmax = fmaxf(lmax, __shfl_xor_sync(0xffu, lmax, 4));
        if (tid == 0) atomicMax(&g_kmax_u, fenc(lmax));
    }
}

// ------------------------------ k2: context + kmean ------------------------
__global__ __launch_bounds__(256) void k2_context(const float* __restrict__ V) {
    __shared__ __align__(16) unsigned kp_u[64][72];  // [n-local][m-local] tf32
    __shared__ __align__(16) unsigned v_u[64][72];   // [n-local][e] tf32
    __shared__ float d_s[64];
    __shared__ float msum_s[64];

    int tid = threadIdx.x, lane = tid & 31, warp = tid >> 5;
    int g = lane >> 2, tg = lane & 3;
    int m0 = blockIdx.x << 6, bh = blockIdx.y, cbase = blockIdx.z << 4;
    int mh = (warp & 1) << 5;        // m rows 32*wh
    int eb = (warp >> 1) << 4;       // e cols 16*we
    int col = tid & 63, rr = tid >> 6;
    bool cvalid = (m0 + col) < MDIM;

    float stab = fdec(g_kmax_u);
    if (tid < 64) msum_s[tid] = 0.f;

    float acc[2][2][4];
#pragma unroll
    for (int i = 0; i < 2; i++)
#pragma unroll
        for (int j = 0; j < 2; j++)
#pragma unroll
            for (int q = 0; q < 4; q++) acc[i][j][q] = 0.f;

    for (int nc = 0; nc < 16; nc++) {
        int n0 = (cbase + nc) << 6;
        __syncthreads();   // previous GEMM done with kp_u / v_u

        const float* vb = V + ((size_t)bh * NSEQ + n0) * EDIM;
#pragma unroll
        for (int t = 0; t < 4; t++) {
            int idx = tid + (t << 8);
            int r = idx >> 4, c4 = (idx & 15) << 2;
            float4 v = *(const float4*)(vb + (size_t)r * 64 + c4);
            uint4 u;
            u.x = f2tf(v.x); u.y = f2tf(v.y); u.z = f2tf(v.z); u.w = f2tf(v.w);
            *(uint4*)&v_u[r][c4] = u;
        }
        if (tid < 64) d_s[tid] = g_diag_k[bh * NSEQ + n0 + tid];

        float raw[16];
        const float* kdb = g_kdash + ((size_t)bh * NSEQ + n0) * MDIM + m0 + col;
#pragma unroll
        for (int t = 0; t < 16; t++) {
            int r = rr + (t << 2);
            raw[t] = cvalid ? kdb[(size_t)r * MDIM] : 0.f;
        }
        __syncthreads();   // d_s, v_u ready

        float local = 0.f;
#pragma unroll
        for (int t = 0; t < 16; t++) {
            int r = rr + (t << 2);
            float val = RATIO_F * (__expf(raw[t] - d_s[r] - stab) + EPS_F);
            kp_u[r][col] = f2tf(val);
            local += val;
        }
        atomicAdd(&msum_s[col], local);
        __syncthreads();   // kp_u ready

        // C[64m x 64e] += kp^T @ v  over k = 64 local n
#pragma unroll
        for (int ks = 0; ks < 8; ks++) {
            int k0 = ks << 3;
            unsigned a[2][4], b[2][2];
#pragma unroll
            for (int i = 0; i < 2; i++) {
                int mr = mh + (i << 4);
                a[i][0] = kp_u[k0 + tg][mr + g];
                a[i][1] = kp_u[k0 + tg][mr + g + 8];
                a[i][2] = kp_u[k0 + tg + 4][mr + g];
                a[i][3] = kp_u[k0 + tg + 4][mr + g + 8];
            }
#pragma unroll
            for (int j = 0; j < 2; j++) {
                int ec = eb + (j << 3) + g;
                b[j][0] = v_u[k0 + tg][ec];
                b[j][1] = v_u[k0 + tg + 4][ec];
            }
#pragma unroll
            for (int i = 0; i < 2; i++)
#pragma unroll
                for (int j = 0; j < 2; j++)
                    mma8(acc[i][j], a[i][0], a[i][1], a[i][2], a[i][3],
                         b[j][0], b[j][1]);
        }
    }
    __syncthreads();

#pragma unroll
    for (int i = 0; i < 2; i++) {
        int mbase = m0 + mh + (i << 4);
#pragma unroll
        for (int j = 0; j < 2; j++) {
            int e = eb + (j << 3) + (tg << 1);
            int m = mbase + g;
            if (m < MDIM) {
                float* p = g_context + ((size_t)bh * MDIM + m) * EDIM + e;
                atomicAdd(p + 0, acc[i][j][0] * INV_L);
                atomicAdd(p + 1, acc[i][j][1] * INV_L);
            }
            if (m + 8 < MDIM) {
                float* p = g_context + ((size_t)bh * MDIM + m + 8) * EDIM + e;
                atomicAdd(p + 0, acc[i][j][2] * INV_L);
                atomicAdd(p + 1, acc[i][j][3] * INV_L);
            }
        }
    }
    if (tid < 64 && cvalid)
        atomicAdd(&g_kmean[bh * MDIM + m0 + tid], msum_s[tid] * INV_L);
}

// ------------------------------ k3: output ---------------------------------
constexpr int SM3_QP_W = MPAD * 72;           // 19584 words: qp[272][72]
constexpr int SM3_TQ_W = 64 * 72;             // 4608
constexpr int SM3_TP_W = 64 * 72;             // 4608
constexpr int SM3_WORDS = SM3_QP_W + SM3_TQ_W + SM3_TP_W + 128;
constexpr int SM3_BYTES = SM3_WORDS * 4;      // 115,712 B -> 2 CTAs/SM

__global__ __launch_bounds__(256) void k3_out(const float* __restrict__ Q,
                                              const float* __restrict__ Pm,
                                              float* __restrict__ Out) {
    extern __shared__ __align__(16) unsigned smu[];
    unsigned* qp = smu;                                         // [272][72]
    unsigned (*TQ)[72] = (unsigned(*)[72])(smu + SM3_QP_W);     // Q tile / km alias
    unsigned (*TP)[72] = (unsigned(*)[72])(smu + SM3_QP_W + SM3_TQ_W); // P / context
    float* dq   = (float*)(smu + SM3_QP_W + SM3_TQ_W + SM3_TP_W);
    float* dinv = dq + 64;
    float* km   = (float*)TQ;   // valid after phase 1

    int tid = threadIdx.x, lane = tid & 31, warp = tid >> 5;
    int g = lane >> 2, tg = lane & 3;
    int bh = blockIdx.y, n0 = blockIdx.x << 6;
    int rb = (warp & 1) << 5;
    int cb = (warp >> 1) << 4;

    load_tile_diag(TQ, Q + ((size_t)bh * NSEQ + n0) * DDIM, tid, dq);

    // ---- phase 1: q_dash -> qp[m][r] (raw fp32 bits) ----
    for (int mc = 0; mc < 5; mc++) {
        int m0 = mc << 6;
        __syncthreads();
        load_tile(TP, Pm + (size_t)m0 * DDIM, MDIM - m0, tid);
        __syncthreads();

        float c[2][2][4];
#pragma unroll
        for (int i = 0; i < 2; i++)
#pragma unroll
            for (int j = 0; j < 2; j++)
#pragma unroll
                for (int q = 0; q < 4; q++) c[i][j][q] = 0.f;

#pragma unroll
        for (int ks = 0; ks < 8; ks++) {
            int k0 = ks << 3;
            unsigned a[2][4], b[2][2];
#pragma unroll
            for (int i = 0; i < 2; i++) {
                int r0 = rb + (i << 4);
                a[i][0] = TQ[r0 + g][k0 + tg];
                a[i][1] = TQ[r0 + g + 8][k0 + tg];
                a[i][2] = TQ[r0 + g][k0 + tg + 4];
                a[i][3] = TQ[r0 + g + 8][k0 + tg + 4];
            }
#pragma unroll
            for (int j = 0; j < 2; j++) {
                int mcol = cb + (j << 3) + g;
                b[j][0] = TP[mcol][k0 + tg];
                b[j][1] = TP[mcol][k0 + tg + 4];
            }
#pragma unroll
            for (int i = 0; i < 2; i++)
#pragma unroll
                for (int j = 0; j < 2; j++)
                    mma8(c[i][j], a[i][0], a[i][1], a[i][2], a[i][3],
                         b[j][0], b[j][1]);
        }
#pragma unroll
        for (int i = 0; i < 2; i++) {
            int r = rb + (i << 4) + g;
#pragma unroll
            for (int j = 0; j < 2; j++) {
                int m = m0 + cb + (j << 3) + (tg << 1);
                if (m < MPAD) {   // m even <= 270; pair fits
                    qp[m * 72 + r]           = __float_as_uint(c[i][j][0] * DN_F);
                    qp[(m + 1) * 72 + r]     = __float_as_uint(c[i][j][1] * DN_F);
                    qp[m * 72 + r + 8]       = __float_as_uint(c[i][j][2] * DN_F);
                    qp[(m + 1) * 72 + r + 8] = __float_as_uint(c[i][j][3] * DN_F);
                }
            }
        }
    }
    __syncthreads();
    for (int i = tid; i < MDIM; i += 256) km[i] = g_kmean[bh * MDIM + i];
    __syncthreads();

    // ---- phase 2: per-row max, exp, D_inv; qp -> tf32 ----
    {
        int r = tid >> 2, g4 = tid & 3;
        float mx = -3.0e38f;
        for (int cc = g4; cc < MDIM; cc += 4)
            mx = fmaxf(mx, __uint_as_float(qp[cc * 72 + r]));
        mx = fmaxf(mx, __shfl_xor_sync(0xffffffffu, mx, 1));
        mx = fmaxf(mx, __shfl_xor_sync(0xffffffffu, mx, 2));

        float dqr = dq[r];
        float dsum = 0.f;
        for (int cc = g4; cc < MDIM; cc += 4) {
            float val = RATIO_F *
                (__expf(__uint_as_float(qp[cc * 72 + r]) - dqr - mx) + EPS_F);
            qp[cc * 72 + r] = f2tf(val);
            dsum += val * km[cc];
        }
        dsum += __shfl_xor_sync(0xffffffffu, dsum, 1);
        dsum += __shfl_xor_sync(0xffffffffu, dsum, 2);
        if (g4 == 0) dinv[r] = 1.0f / dsum;
    }

    // ---- phase 3: out = (qp @ context) * dinv ----
    float c[2][2][4];
#pragma unroll
    for (int i = 0; i < 2; i++)
#pragma unroll
        for (int j = 0; j < 2; j++)
#pragma unroll
            for (int q = 0; q < 4; q++) c[i][j][q] = 0.f;

    for (int kc = 0; kc < 5; kc++) {
        int k00 = kc << 6;
        int ksteps = (kc < 4) ? 8 : 2;   // 4*64 + 16 = 272 padded k
        __syncthreads();
        load_tile(TP, g_context + ((size_t)bh * MDIM + k00) * EDIM,
                  MDIM - k00, tid);
        __syncthreads();

        for (int ks = 0; ks < ksteps; ks++) {
            int kl = ks << 3;
            unsigned a[2][4], b[2][2];
#pragma unroll
            for (int i = 0; i < 2; i++) {
                int r0 = rb + (i << 4);
                a[i][0] = qp[(k00 + kl + tg) * 72 + r0 + g];
                a[i][1] = qp[(k00 + kl + tg) * 72 + r0 + g + 8];
                a[i][2] = qp[(k00 + kl + tg + 4) * 72 + r0 + g];
                a[i][3] = qp[(k00 + kl + tg + 4) * 72 + r0 + g + 8];
            }
#pragma unroll
            for (int j = 0; j < 2; j++) {
                int ec = cb + (j << 3) + g;
                b[j][0] = TP[kl + tg][ec];
                b[j][1] = TP[kl + tg + 4][ec];
            }
#pragma unroll
            for (int i = 0; i < 2; i++)
#pragma unroll
                for (int j = 0; j < 2; j++)
                    mma8(c[i][j], a[i][0], a[i][1], a[i][2], a[i][3],
                         b[j][0], b[j][1]);
        }
    }

#pragma unroll
    for (int i = 0; i < 2; i++) {
        int r = rb + (i << 4) + g;
        float d0 = dinv[r], d1 = dinv[r + 8];
#pragma unroll
        for (int j = 0; j < 2; j++) {
            int e = cb + (j << 3) + (tg << 1);
            float2 v0 = make_float2(c[i][j][0] * d0, c[i][j][1] * d0);
            float2 v1 = make_float2(c[i][j][2] * d1, c[i][j][3] * d1);
            *(float2*)(Out + ((size_t)bh * NSEQ + n0 + r) * EDIM + e)     = v0;
            *(float2*)(Out + ((size_t)bh * NSEQ + n0 + r + 8) * EDIM + e) = v1;
        }
    }
}

// ------------------------------ launch -------------------------------------
extern "C" void kernel_launch(void* const* d_in, const int* in_sizes, int n_in,
                              void* d_out, int out_size) {
    const float* q = (const float*)d_in[0];
    const float* k = (const float*)d_in[1];
    const float* v = (const float*)d_in[2];
    const float* P = (const float*)d_in[3];
    float* out = (float*)d_out;

    cudaFuncSetAttribute(k3_out, cudaFuncAttributeMaxDynamicSharedMemorySize,
                         SM3_BYTES);

    k0_init<<<256, 256>>>();
    k1_kdash<<<dim3(NSEQ / 64, BH), 256>>>(k, P);
    k2_context<<<dim3(5, BH, 4), 256>>>(v);
    k3_out<<<dim3(NSEQ / 64, BH), 256, SM3_BYTES>>>(q, P, out);
}

// round 6
// speedup vs baseline: 4.3300x; 1.1423x over previous
#include <cuda_runtime.h>
#include <cuda_bf16.h>
#include <cstdint>

// ---------------------------------------------------------------------------
// FastAttention (Performer / FAVOR+) — TF32 warp-MMA, conflict-free strides
//   b=4, h=8 (BH=32), n=4096, d=64, m=266, e=64
// Bank rule: fragment loads with g(lane>>2)-indexed rows need stride%32==4
// (68); with tg-indexed rows need stride%32==8 (72).
// ---------------------------------------------------------------------------

#define BH    32
#define NSEQ  4096
#define DDIM  64
#define MDIM  266
#define EDIM  64
#define MPAD  272

constexpr float DN_F    = 0.35355339059327373f;  // 64^-0.25
constexpr float DIAG_C  = 0.0625f;               // 0.5 * DN^2
constexpr float RATIO_F = 0.06131393316f;        // 266^-0.5
constexpr float EPS_F   = 1e-4f;
constexpr float INV_L   = 1.0f / 4096.0f;

// ------------------------------ scratch ------------------------------------
__device__ __align__(16) float    g_kdash[(size_t)BH * NSEQ * MDIM]; // 139.5 MB
__device__ __align__(16) float    g_diag_k[BH * NSEQ];
__device__ unsigned               g_kmax_u;
__device__ __align__(16) float    g_context[BH * MDIM * EDIM];
__device__ __align__(16) float    g_kmean[BH * MDIM];

__device__ __forceinline__ unsigned fenc(float f) {
    unsigned u = __float_as_uint(f);
    return (u & 0x80000000u) ? ~u : (u | 0x80000000u);
}
__device__ __forceinline__ float fdec(unsigned k) {
    return (k & 0x80000000u) ? __uint_as_float(k ^ 0x80000000u)
                             : __uint_as_float(~k);
}
__device__ __forceinline__ unsigned f2tf(float x) {
    unsigned r;
    asm("cvt.rna.tf32.f32 %0, %1;" : "=r"(r) : "f"(x));
    return r;
}
__device__ __forceinline__ void mma8(float* c, unsigned a0, unsigned a1,
                                     unsigned a2, unsigned a3,
                                     unsigned b0, unsigned b1) {
    asm volatile(
        "mma.sync.aligned.m16n8k8.row.col.f32.tf32.tf32.f32 "
        "{%0,%1,%2,%3}, {%4,%5,%6,%7}, {%8,%9}, {%0,%1,%2,%3};"
        : "+f"(c[0]), "+f"(c[1]), "+f"(c[2]), "+f"(c[3])
        : "r"(a0), "r"(a1), "r"(a2), "r"(a3), "r"(b0), "r"(b1));
}

// 64x64 fp32 -> tf32 tile at row stride S (words). 256 threads.
__device__ __forceinline__ void load_tileS(unsigned* dst, int S,
                                           const float* __restrict__ src,
                                           int valid, int tid) {
#pragma unroll
    for (int t = 0; t < 4; t++) {
        int idx = tid + (t << 8);
        int r = idx >> 4, c4 = (idx & 15) << 2;
        float4 v = (r < valid) ? *(const float4*)(src + (size_t)r * 64 + c4)
                               : make_float4(0.f, 0.f, 0.f, 0.f);
        uint4 u;
        u.x = f2tf(v.x); u.y = f2tf(v.y); u.z = f2tf(v.z); u.w = f2tf(v.w);
        *(uint4*)&dst[r * S + c4] = u;
    }
}
// same (64 valid rows) + DIAG_C * sum(row^2) of ORIGINAL fp32 -> diag_out[r]
__device__ __forceinline__ void load_tile_diagS(unsigned* dst, int S,
                                                const float* __restrict__ src,
                                                int tid, float* diag_out) {
#pragma unroll
    for (int t = 0; t < 4; t++) {
        int idx = tid + (t << 8);
        int r = idx >> 4, c4 = (idx & 15) << 2;
        float4 v = *(const float4*)(src + (size_t)r * 64 + c4);
        float s = v.x * v.x + v.y * v.y + v.z * v.z + v.w * v.w;
        s += __shfl_xor_sync(0xffffffffu, s, 1);
        s += __shfl_xor_sync(0xffffffffu, s, 2);
        s += __shfl_xor_sync(0xffffffffu, s, 4);
        s += __shfl_xor_sync(0xffffffffu, s, 8);
        uint4 u;
        u.x = f2tf(v.x); u.y = f2tf(v.y); u.z = f2tf(v.z); u.w = f2tf(v.w);
        *(uint4*)&dst[r * S + c4] = u;
        if ((tid & 15) == 0) diag_out[r] = DIAG_C * s;
    }
}

// ------------------------------ k0: init -----------------------------------
__global__ void k0_init() {
    int i = blockIdx.x * blockDim.x + threadIdx.x;
    int stride = gridDim.x * blockDim.x;
    if (i == 0) g_kmax_u = 0u;
    for (int t = i; t < BH * MDIM * EDIM; t += stride) g_context[t] = 0.f;
    for (int t = i; t < BH * MDIM; t += stride)        g_kmean[t] = 0.f;
}

// ------------------------------ k1: k_dash ---------------------------------
// CTA: 128 n-rows x 64 m-chunk; 8 warps = 4(n) x 2(m) grid of 32x32 tiles.
constexpr int K1_KS_W = 128 * 68;        // 8704
constexpr int K1_PS_W = 64 * 68;         // 4352
constexpr int K1_WORDS = K1_KS_W + K1_PS_W + 8;
constexpr int K1_BYTES = K1_WORDS * 4;   // 52,256 B

__global__ __launch_bounds__(256) void k1_kdash(const float* __restrict__ K,
                                                const float* __restrict__ Pm) {
    extern __shared__ __align__(16) unsigned k1s[];
    unsigned* Ks = k1s;                 // [128][68]
    unsigned* Ps = k1s + K1_KS_W;       // [64][68]
    float* red = (float*)(k1s + K1_KS_W + K1_PS_W);

    int tid = threadIdx.x, lane = tid & 31, warp = tid >> 5;
    int g = lane >> 2, tg = lane & 3;
    int bh = blockIdx.y, n0 = blockIdx.x << 7;
    int nr = (warp >> 1) << 5;          // 0,32,64,96
    int cb = (warp & 1) << 5;           // 0,32

    const float* kb = K + ((size_t)bh * NSEQ + n0) * DDIM;
    float* dgp = g_diag_k + bh * NSEQ + n0;
    load_tile_diagS(Ks, 68, kb, tid, dgp);
    load_tile_diagS(Ks + 64 * 68, 68, kb + (size_t)64 * DDIM, tid, dgp + 64);

    float lmax = -3.0e38f;
    for (int mc = 0; mc < 5; mc++) {
        int m0 = mc << 6;
        __syncthreads();
        load_tileS(Ps, 68, Pm + (size_t)m0 * DDIM, MDIM - m0, tid);
        __syncthreads();

        float c[2][4][4];
#pragma unroll
        for (int i = 0; i < 2; i++)
#pragma unroll
            for (int j = 0; j < 4; j++)
#pragma unroll
                for (int q = 0; q < 4; q++) c[i][j][q] = 0.f;

#pragma unroll
        for (int ks = 0; ks < 8; ks++) {
            int k0 = ks << 3;
            unsigned a[2][4], b[4][2];
#pragma unroll
            for (int i = 0; i < 2; i++) {
                int r0 = nr + (i << 4);
                a[i][0] = Ks[(r0 + g) * 68 + k0 + tg];
                a[i][1] = Ks[(r0 + g + 8) * 68 + k0 + tg];
                a[i][2] = Ks[(r0 + g) * 68 + k0 + tg + 4];
                a[i][3] = Ks[(r0 + g + 8) * 68 + k0 + tg + 4];
            }
#pragma unroll
            for (int j = 0; j < 4; j++) {
                int mcol = cb + (j << 3) + g;
                b[j][0] = Ps[mcol * 68 + k0 + tg];
                b[j][1] = Ps[mcol * 68 + k0 + tg + 4];
            }
#pragma unroll
            for (int i = 0; i < 2; i++)
#pragma unroll
                for (int j = 0; j < 4; j++)
                    mma8(c[i][j], a[i][0], a[i][1], a[i][2], a[i][3],
                         b[j][0], b[j][1]);
        }

#pragma unroll
        for (int i = 0; i < 2; i++) {
            int row = n0 + nr + (i << 4) + g;
#pragma unroll
            for (int j = 0; j < 4; j++) {
                int m = m0 + cb + (j << 3) + (tg << 1);
                if (m < MDIM) {
                    float2 v0 = make_float2(c[i][j][0] * DN_F, c[i][j][1] * DN_F);
                    float2 v1 = make_float2(c[i][j][2] * DN_F, c[i][j][3] * DN_F);
                    lmax = fmaxf(lmax, fmaxf(fmaxf(v0.x, v0.y), fmaxf(v1.x, v1.y)));
                    *(float2*)(g_kdash + ((size_t)bh * NSEQ + row) * MDIM + m)     = v0;
                    *(float2*)(g_kdash + ((size_t)bh * NSEQ + row + 8) * MDIM + m) = v1;
                }
            }
        }
    }

#pragma unroll
    for (int o = 16; o > 0; o >>= 1)
        lmax = fmaxf(lmax, __shfl_xor_sync(0xffffffffu, lmax, o));
    if (lane == 0) red[warp] = lmax;
    __syncthreads();
    if (tid < 8) {
        lmax = red[tid];
        lmax = fmaxf(lmax, __shfl_xor_sync(0xffu, lmax, 1));
        lmax = fmaxf(lmax, __shfl_xor_sync(0xffu, lmax, 2));
        lmax = fmaxf(lmax, __shfl_xor_sync(0xffu, lmax, 4));
        if (tid == 0) atomicMax(&g_kmax_u, fenc(lmax));
    }
}

// ------------------------------ k2: context + kmean (unchanged) ------------
__global__ __launch_bounds__(256) void k2_context(const float* __restrict__ V) {
    __shared__ __align__(16) unsigned kp_u[64][72];
    __shared__ __align__(16) unsigned v_u[64][72];
    __shared__ float d_s[64];
    __shared__ float msum_s[64];

    int tid = threadIdx.x, lane = tid & 31, warp = tid >> 5;
    int g = lane >> 2, tg = lane & 3;
    int m0 = blockIdx.x << 6, bh = blockIdx.y, cbase = blockIdx.z << 4;
    int mh = (warp & 1) << 5;
    int eb = (warp >> 1) << 4;
    int col = tid & 63, rr = tid >> 6;
    bool cvalid = (m0 + col) < MDIM;

    float stab = fdec(g_kmax_u);
    if (tid < 64) msum_s[tid] = 0.f;

    float acc[2][2][4];
#pragma unroll
    for (int i = 0; i < 2; i++)
#pragma unroll
        for (int j = 0; j < 2; j++)
#pragma unroll
            for (int q = 0; q < 4; q++) acc[i][j][q] = 0.f;

    for (int nc = 0; nc < 16; nc++) {
        int n0 = (cbase + nc) << 6;
        __syncthreads();

        const float* vb = V + ((size_t)bh * NSEQ + n0) * EDIM;
#pragma unroll
        for (int t = 0; t < 4; t++) {
            int idx = tid + (t << 8);
            int r = idx >> 4, c4 = (idx & 15) << 2;
            float4 v = *(const float4*)(vb + (size_t)r * 64 + c4);
            uint4 u;
            u.x = f2tf(v.x); u.y = f2tf(v.y); u.z = f2tf(v.z); u.w = f2tf(v.w);
            *(uint4*)&v_u[r][c4] = u;
        }
        if (tid < 64) d_s[tid] = g_diag_k[bh * NSEQ + n0 + tid];

        float raw[16];
        const float* kdb = g_kdash + ((size_t)bh * NSEQ + n0) * MDIM + m0 + col;
#pragma unroll
        for (int t = 0; t < 16; t++) {
            int r = rr + (t << 2);
            raw[t] = cvalid ? kdb[(size_t)r * MDIM] : 0.f;
        }
        __syncthreads();

        float local = 0.f;
#pragma unroll
        for (int t = 0; t < 16; t++) {
            int r = rr + (t << 2);
            float val = RATIO_F * (__expf(raw[t] - d_s[r] - stab) + EPS_F);
            kp_u[r][col] = f2tf(val);
            local += val;
        }
        atomicAdd(&msum_s[col], local);
        __syncthreads();

#pragma unroll
        for (int ks = 0; ks < 8; ks++) {
            int k0 = ks << 3;
            unsigned a[2][4], b[2][2];
#pragma unroll
            for (int i = 0; i < 2; i++) {
                int mr = mh + (i << 4);
                a[i][0] = kp_u[k0 + tg][mr + g];
                a[i][1] = kp_u[k0 + tg][mr + g + 8];
                a[i][2] = kp_u[k0 + tg + 4][mr + g];
                a[i][3] = kp_u[k0 + tg + 4][mr + g + 8];
            }
#pragma unroll
            for (int j = 0; j < 2; j++) {
                int ec = eb + (j << 3) + g;
                b[j][0] = v_u[k0 + tg][ec];
                b[j][1] = v_u[k0 + tg + 4][ec];
            }
#pragma unroll
            for (int i = 0; i < 2; i++)
#pragma unroll
                for (int j = 0; j < 2; j++)
                    mma8(acc[i][j], a[i][0], a[i][1], a[i][2], a[i][3],
                         b[j][0], b[j][1]);
        }
    }
    __syncthreads();

#pragma unroll
    for (int i = 0; i < 2; i++) {
        int mbase = m0 + mh + (i << 4);
#pragma unroll
        for (int j = 0; j < 2; j++) {
            int e = eb + (j << 3) + (tg << 1);
            int m = mbase + g;
            if (m < MDIM) {
                float* p = g_context + ((size_t)bh * MDIM + m) * EDIM + e;
                atomicAdd(p + 0, acc[i][j][0] * INV_L);
                atomicAdd(p + 1, acc[i][j][1] * INV_L);
            }
            if (m + 8 < MDIM) {
                float* p = g_context + ((size_t)bh * MDIM + m + 8) * EDIM + e;
                atomicAdd(p + 0, acc[i][j][2] * INV_L);
                atomicAdd(p + 1, acc[i][j][3] * INV_L);
            }
        }
    }
    if (tid < 64 && cvalid)
        atomicAdd(&g_kmean[bh * MDIM + m0 + tid], msum_s[tid] * INV_L);
}

// ------------------------------ k3: output ---------------------------------
constexpr int SM3_QP_W = MPAD * 72;                // 19584: qp[272][72]
constexpr int SM3_TQ_W = 64 * 68;                  // 4352: Q tile / obuf alias
constexpr int SM3_TP_W = 64 * 72;                  // 4608: P(68) / context(72) / km
constexpr int SM3_WMAX = 4 * 64;                   // 256
constexpr int SM3_WORDS = SM3_QP_W + SM3_TQ_W + SM3_TP_W + SM3_WMAX + 64 + 64;
constexpr int SM3_BYTES = SM3_WORDS * 4;           // 115,712 B (2 CTAs/SM)

__global__ __launch_bounds__(256) void k3_out(const float* __restrict__ Q,
                                              const float* __restrict__ Pm,
                                              float* __restrict__ Out) {
    extern __shared__ __align__(16) unsigned smu[];
    unsigned* qp   = smu;                               // stride 72
    unsigned* TQ68 = smu + SM3_QP_W;                    // [64][68]
    float*    OB68 = (float*)TQ68;                      // phase-3 reduce buffer
    unsigned* TP   = smu + SM3_QP_W + SM3_TQ_W;         // [64][68] or [64][72]
    float*    km   = (float*)TP;                        // phase-2 alias
    float*    wmax = (float*)(smu + SM3_QP_W + SM3_TQ_W + SM3_TP_W);
    float*    dq   = wmax + SM3_WMAX;
    float*    dinv = dq + 64;

    int tid = threadIdx.x, lane = tid & 31, warp = tid >> 5;
    int g = lane >> 2, tg = lane & 3;
    int bh = blockIdx.y, n0 = blockIdx.x << 6;
    int rb = (warp & 1) << 5;      // phase-1 n slab
    int cb = (warp >> 1) << 4;     // phase-1 m slab (16 wide)

    load_tile_diagS(TQ68, 68, Q + ((size_t)bh * NSEQ + n0) * DDIM, tid, dq);

    // ---- phase 1: q_dash -> qp[m][r] raw fp32; row-max in registers ----
    float rmax[2][2] = {{-3.0e38f, -3.0e38f}, {-3.0e38f, -3.0e38f}};
    for (int mc = 0; mc < 5; mc++) {
        int m0 = mc << 6;
        __syncthreads();
        load_tileS(TP, 68, Pm + (size_t)m0 * DDIM, MDIM - m0, tid);
        __syncthreads();

        float c[2][2][4];
#pragma unroll
        for (int i = 0; i < 2; i++)
#pragma unroll
            for (int j = 0; j < 2; j++)
#pragma unroll
                for (int q = 0; q < 4; q++) c[i][j][q] = 0.f;

#pragma unroll
        for (int ks = 0; ks < 8; ks++) {
            int k0 = ks << 3;
            unsigned a[2][4], b[2][2];
#pragma unroll
            for (int i = 0; i < 2; i++) {
                int r0 = rb + (i << 4);
                a[i][0] = TQ68[(r0 + g) * 68 + k0 + tg];
                a[i][1] = TQ68[(r0 + g + 8) * 68 + k0 + tg];
                a[i][2] = TQ68[(r0 + g) * 68 + k0 + tg + 4];
                a[i][3] = TQ68[(r0 + g + 8) * 68 + k0 + tg + 4];
            }
#pragma unroll
            for (int j = 0; j < 2; j++) {
                int mcol = cb + (j << 3) + g;
                b[j][0] = TP[mcol * 68 + k0 + tg];
                b[j][1] = TP[mcol * 68 + k0 + tg + 4];
            }
#pragma unroll
            for (int i = 0; i < 2; i++)
#pragma unroll
                for (int j = 0; j < 2; j++)
                    mma8(c[i][j], a[i][0], a[i][1], a[i][2], a[i][3],
                         b[j][0], b[j][1]);
        }
#pragma unroll
        for (int i = 0; i < 2; i++) {
            int r = rb + (i << 4) + g;
#pragma unroll
            for (int j = 0; j < 2; j++) {
                int m = m0 + cb + (j << 3) + (tg << 1);
                if (m < MPAD) {
                    float v0 = c[i][j][0] * DN_F, v1 = c[i][j][1] * DN_F;
                    float v2 = c[i][j][2] * DN_F, v3 = c[i][j][3] * DN_F;
                    qp[m * 72 + r]           = __float_as_uint(v0);
                    qp[(m + 1) * 72 + r]     = __float_as_uint(v1);
                    qp[m * 72 + r + 8]       = __float_as_uint(v2);
                    qp[(m + 1) * 72 + r + 8] = __float_as_uint(v3);
                    if (m < MDIM) {
                        rmax[i][0] = fmaxf(rmax[i][0], fmaxf(v0, v1));
                        rmax[i][1] = fmaxf(rmax[i][1], fmaxf(v2, v3));
                    }
                }
            }
        }
    }
    // per-warp row maxes -> wmax[warp>>1][row]
#pragma unroll
    for (int i = 0; i < 2; i++)
#pragma unroll
        for (int h = 0; h < 2; h++) {
            float v = rmax[i][h];
            v = fmaxf(v, __shfl_xor_sync(0xffffffffu, v, 1));
            v = fmaxf(v, __shfl_xor_sync(0xffffffffu, v, 2));
            if (tg == 0)
                wmax[(warp >> 1) * 64 + rb + (i << 4) + g + (h << 3)] = v;
        }
    for (int i = tid; i < MDIM; i += 256) km[i] = g_kmean[bh * MDIM + i];
    __syncthreads();

    // ---- phase 2: exp + D_inv (single pass; max from wmax) ----
    {
        int r = tid >> 2, g4 = tid & 3;
        float mx = fmaxf(fmaxf(wmax[r], wmax[64 + r]),
                         fmaxf(wmax[128 + r], wmax[192 + r]));
        float dqr = dq[r];
        float dsum = 0.f;
        for (int cc = g4; cc < MDIM; cc += 4) {
            float val = RATIO_F *
                (__expf(__uint_as_float(qp[cc * 72 + r]) - dqr - mx) + EPS_F);
            qp[cc * 72 + r] = f2tf(val);
            dsum += val * km[cc];
        }
        dsum += __shfl_xor_sync(0xffffffffu, dsum, 1);
        dsum += __shfl_xor_sync(0xffffffffu, dsum, 2);
        if (g4 == 0) dinv[r] = 1.0f / dsum;
    }

    // ---- phase 3: out = (qp @ context) * dinv, split-k warp pairs ----
    int sub = warp >> 2;            // 0: first half of k-steps, 1: second
    int wg  = warp & 3;
    int rb2 = (wg & 1) << 5;
    int eb2 = (wg >> 1) << 5;

    float c[2][4][4];
#pragma unroll
    for (int i = 0; i < 2; i++)
#pragma unroll
        for (int j = 0; j < 4; j++)
#pragma unroll
            for (int q = 0; q < 4; q++) c[i][j][q] = 0.f;

    for (int kc = 0; kc < 5; kc++) {
        int k00 = kc << 6;
        int half = (kc < 4) ? 4 : 1;          // half the k-steps of this chunk
        __syncthreads();
        load_tileS(TP, 72, g_context + ((size_t)bh * MDIM + k00) * EDIM,
                   MDIM - k00, tid);
        __syncthreads();

        int ks0 = sub * half, ks1 = ks0 + half;
        for (int ks = ks0; ks < ks1; ks++) {
            int kl = ks << 3;
            unsigned a[2][4], b[4][2];
#pragma unroll
            for (int i = 0; i < 2; i++) {
                int r0 = rb2 + (i << 4);
                a[i][0] = qp[(k00 + kl + tg) * 72 + r0 + g];
                a[i][1] = qp[(k00 + kl + tg) * 72 + r0 + g + 8];
                a[i][2] = qp[(k00 + kl + tg + 4) * 72 + r0 + g];
                a[i][3] = qp[(k00 + kl + tg + 4) * 72 + r0 + g + 8];
            }
#pragma unroll
            for (int j = 0; j < 4; j++) {
                int ec = eb2 + (j << 3) + g;
                b[j][0] = TP[(kl + tg) * 72 + ec];
                b[j][1] = TP[(kl + tg + 4) * 72 + ec];
            }
#pragma unroll
            for (int i = 0; i < 2; i++)
#pragma unroll
                for (int j = 0; j < 4; j++)
                    mma8(c[i][j], a[i][0], a[i][1], a[i][2], a[i][3],
                         b[j][0], b[j][1]);
        }
    }

    // reduce sub0 + sub1 via smem, scale by dinv, store
    __syncthreads();
    if (sub == 0) {
#pragma unroll
        for (int i = 0; i < 2; i++) {
            int row = rb2 + (i << 4) + g;
#pragma unroll
            for (int j = 0; j < 4; j++) {
                int col = eb2 + (j << 3) + (tg << 1);
                OB68[row * 68 + col]           = c[i][j][0];
                OB68[row * 68 + col + 1]       = c[i][j][1];
                OB68[(row + 8) * 68 + col]     = c[i][j][2];
                OB68[(row + 8) * 68 + col + 1] = c[i][j][3];
            }
        }
    }
    __syncthreads();
    if (sub == 1) {
#pragma unroll
        for (int i = 0; i < 2; i++) {
            int row = rb2 + (i << 4) + g;
            float d0 = dinv[row], d1 = dinv[row + 8];
#pragma unroll
            for (int j = 0; j < 4; j++) {
                int col = eb2 + (j << 3) + (tg << 1);
                float2 v0, v1;
                v0.x = (c[i][j][0] + OB68[row * 68 + col])           * d0;
                v0.y = (c[i][j][1] + OB68[row * 68 + col + 1])       * d0;
                v1.x = (c[i][j][2] + OB68[(row + 8) * 68 + col])     * d1;
                v1.y = (c[i][j][3] + OB68[(row + 8) * 68 + col + 1]) * d1;
                *(float2*)(Out + ((size_t)bh * NSEQ + n0 + row) * EDIM + col)     = v0;
                *(float2*)(Out + ((size_t)bh * NSEQ + n0 + row + 8) * EDIM + col) = v1;
            }
        }
    }
}

// ------------------------------ launch -------------------------------------
extern "C" void kernel_launch(void* const* d_in, const int* in_sizes, int n_in,
                              void* d_out, int out_size) {
    const float* q = (const float*)d_in[0];
    const float* k = (const float*)d_in[1];
    const float* v = (const float*)d_in[2];
    const float* P = (const float*)d_in[3];
    float* out = (float*)d_out;

    cudaFuncSetAttribute(k1_kdash, cudaFuncAttributeMaxDynamicSharedMemorySize,
                         K1_BYTES);
    cudaFuncSetAttribute(k3_out, cudaFuncAttributeMaxDynamicSharedMemorySize,
                         SM3_BYTES);

    k0_init<<<256, 256>>>();
    k1_kdash<<<dim3(NSEQ / 128, BH), 256, K1_BYTES>>>(k, P);
    k2_context<<<dim3(5, BH, 4), 256>>>(v);
    k3_out<<<dim3(NSEQ / 64, BH), 256, SM3_BYTES>>>(q, P, out);
}